// round 2
// baseline (speedup 1.0000x reference)
#include <cuda_runtime.h>
#include <math.h>

// ---------------------------------------------------------------------------
// Problem constants
// ---------------------------------------------------------------------------
#define D_MODEL   1024
#define NUM_HEADS 16
#define HEAD_DIM  64
#define BATCH     2
#define SEQ       2048
#define M_ROWS    (BATCH * SEQ)      // 4096

// ---------------------------------------------------------------------------
// Scratch (static device globals; no cudaMalloc allowed)
// ---------------------------------------------------------------------------
__device__ float g_q[M_ROWS * D_MODEL];
__device__ float g_k[M_ROWS * D_MODEL];
__device__ float g_v[M_ROWS * D_MODEL];
__device__ float g_attn[M_ROWS * D_MODEL];

// ---------------------------------------------------------------------------
// GEMM: C[M,N] = A[M,K] @ W[K,N] + bias[N]
// 128x128 block tile, BK=8, 256 threads, 8x8 per-thread register tile.
// ---------------------------------------------------------------------------
#define BM 128
#define BN 128
#define BK 8
#define TM 8
#define TN 8

__global__ __launch_bounds__(256)
void gemm_bias_kernel(const float* __restrict__ A,
                      const float* __restrict__ W,
                      const float* __restrict__ bias,
                      float* __restrict__ C,
                      int M, int N, int K) {
    __shared__ float As[BK][BM];   // transposed A tile
    __shared__ float Ws[BK][BN];

    const int tid = threadIdx.x;
    const int tx  = tid % 16;          // 0..15 -> column group
    const int ty  = tid / 16;          // 0..15 -> row group
    const int rowBase = blockIdx.y * BM;
    const int colBase = blockIdx.x * BN;

    // A tile load mapping: 128 rows x 8 cols = 256 float4
    const int aRow  = tid >> 1;              // 0..127
    const int aCol4 = (tid & 1) * 4;         // 0 or 4
    // W tile load mapping: 8 rows x 128 cols = 256 float4
    const int wRow  = tid >> 5;              // 0..7
    const int wCol4 = (tid & 31) * 4;        // 0..124

    float acc[TM][TN];
    #pragma unroll
    for (int i = 0; i < TM; i++)
        #pragma unroll
        for (int j = 0; j < TN; j++)
            acc[i][j] = 0.0f;

    for (int k0 = 0; k0 < K; k0 += BK) {
        float4 av = *(const float4*)(A + (size_t)(rowBase + aRow) * K + k0 + aCol4);
        As[aCol4 + 0][aRow] = av.x;
        As[aCol4 + 1][aRow] = av.y;
        As[aCol4 + 2][aRow] = av.z;
        As[aCol4 + 3][aRow] = av.w;

        float4 wv = *(const float4*)(W + (size_t)(k0 + wRow) * N + colBase + wCol4);
        *(float4*)&Ws[wRow][wCol4] = wv;

        __syncthreads();

        #pragma unroll
        for (int k = 0; k < BK; k++) {
            float ra[TM], rb[TN];
            #pragma unroll
            for (int i = 0; i < TM; i++) ra[i] = As[k][ty * TM + i];
            #pragma unroll
            for (int j = 0; j < TN; j++) rb[j] = Ws[k][tx * TN + j];
            #pragma unroll
            for (int i = 0; i < TM; i++)
                #pragma unroll
                for (int j = 0; j < TN; j++)
                    acc[i][j] = fmaf(ra[i], rb[j], acc[i][j]);
        }
        __syncthreads();
    }

    #pragma unroll
    for (int i = 0; i < TM; i++) {
        const int row = rowBase + ty * TM + i;
        #pragma unroll
        for (int j = 0; j < TN; j += 4) {
            const int col = colBase + tx * TN + j;
            float4 bv = *(const float4*)(bias + col);
            float4 cv;
            cv.x = acc[i][j + 0] + bv.x;
            cv.y = acc[i][j + 1] + bv.y;
            cv.z = acc[i][j + 2] + bv.z;
            cv.w = acc[i][j + 3] + bv.w;
            *(float4*)(C + (size_t)row * N + col) = cv;
        }
    }
}

// ---------------------------------------------------------------------------
// Flash attention (fp32 streaming softmax)
// Block: 64 query rows of one (b,h). 256 threads; thread (ty,tx) owns a
// 4x4 patch. Q tile kept in smem (prescaled by 1/sqrt(Dh)); loop over 64-row
// K/V tiles with online softmax.
// smem: Qs, Ks, Vs, Ps each 64 x 68 floats (padded) -> 69632 bytes dynamic.
// ---------------------------------------------------------------------------
#define AQ   64
#define AK   64
#define SPAD 68
#define ATTN_SMEM (4 * AQ * SPAD * 4)

__global__ __launch_bounds__(256)
void flash_attn_kernel(const float* __restrict__ q,
                       const float* __restrict__ k,
                       const float* __restrict__ v,
                       float* __restrict__ o) {
    extern __shared__ float sm[];
    float* Qs = sm;
    float* Ks = Qs + AQ * SPAD;
    float* Vs = Ks + AK * SPAD;
    float* Ps = Vs + AK * SPAD;

    const int tid = threadIdx.x;
    const int tx  = tid % 16;
    const int ty  = tid / 16;
    const int bh  = blockIdx.y;
    const int b   = bh / NUM_HEADS;
    const int h   = bh % NUM_HEADS;
    const int q0  = blockIdx.x * AQ;

    const size_t base = (size_t)b * SEQ * D_MODEL + (size_t)h * HEAD_DIM;
    const float qscale = 0.125f;   // 1/sqrt(64)

    // Load Q tile (prescaled). 64 rows x 64 cols = 1024 float4.
    for (int idx = tid; idx < AQ * HEAD_DIM / 4; idx += 256) {
        int r  = idx / 16;
        int c4 = (idx % 16) * 4;
        float4 vq = *(const float4*)(q + base + (size_t)(q0 + r) * D_MODEL + c4);
        Qs[r * SPAD + c4 + 0] = vq.x * qscale;
        Qs[r * SPAD + c4 + 1] = vq.y * qscale;
        Qs[r * SPAD + c4 + 2] = vq.z * qscale;
        Qs[r * SPAD + c4 + 3] = vq.w * qscale;
    }

    float m_[4], l_[4], accO[4][4];
    #pragma unroll
    for (int i = 0; i < 4; i++) {
        m_[i] = -INFINITY;
        l_[i] = 0.0f;
        #pragma unroll
        for (int j = 0; j < 4; j++) accO[i][j] = 0.0f;
    }

    for (int kt = 0; kt < SEQ / AK; kt++) {
        __syncthreads();   // prior PV done (and Q visible on first iter)

        const int k0r = kt * AK;
        for (int idx = tid; idx < AK * HEAD_DIM / 4; idx += 256) {
            int r  = idx / 16;
            int c4 = (idx % 16) * 4;
            float4 vk = *(const float4*)(k + base + (size_t)(k0r + r) * D_MODEL + c4);
            Ks[r * SPAD + c4 + 0] = vk.x;
            Ks[r * SPAD + c4 + 1] = vk.y;
            Ks[r * SPAD + c4 + 2] = vk.z;
            Ks[r * SPAD + c4 + 3] = vk.w;
            float4 vv = *(const float4*)(v + base + (size_t)(k0r + r) * D_MODEL + c4);
            Vs[r * SPAD + c4 + 0] = vv.x;
            Vs[r * SPAD + c4 + 1] = vv.y;
            Vs[r * SPAD + c4 + 2] = vv.z;
            Vs[r * SPAD + c4 + 3] = vv.w;
        }
        __syncthreads();

        // S = Qs @ Ks^T  (4x4 per thread)
        float s[4][4];
        #pragma unroll
        for (int i = 0; i < 4; i++)
            #pragma unroll
            for (int j = 0; j < 4; j++) s[i][j] = 0.0f;

        for (int d = 0; d < HEAD_DIM; d++) {
            float ra[4], rb[4];
            #pragma unroll
            for (int i = 0; i < 4; i++) ra[i] = Qs[(ty * 4 + i) * SPAD + d];
            #pragma unroll
            for (int j = 0; j < 4; j++) rb[j] = Ks[(tx * 4 + j) * SPAD + d];
            #pragma unroll
            for (int i = 0; i < 4; i++)
                #pragma unroll
                for (int j = 0; j < 4; j++)
                    s[i][j] = fmaf(ra[i], rb[j], s[i][j]);
        }

        // Online softmax per query row (row owned by 16 tx-lanes; butterfly
        // over xor 8,4,2,1 stays within the 16-lane group).
        #pragma unroll
        for (int i = 0; i < 4; i++) {
            float mt = s[i][0];
            #pragma unroll
            for (int j = 1; j < 4; j++) mt = fmaxf(mt, s[i][j]);
            #pragma unroll
            for (int off = 8; off > 0; off >>= 1)
                mt = fmaxf(mt, __shfl_xor_sync(0xffffffffu, mt, off));

            float mnew  = fmaxf(m_[i], mt);
            float alpha = __expf(m_[i] - mnew);

            float lsum = 0.0f;
            #pragma unroll
            for (int j = 0; j < 4; j++) {
                s[i][j] = __expf(s[i][j] - mnew);
                lsum += s[i][j];
            }
            #pragma unroll
            for (int off = 8; off > 0; off >>= 1)
                lsum += __shfl_xor_sync(0xffffffffu, lsum, off);

            l_[i] = l_[i] * alpha + lsum;
            m_[i] = mnew;

            #pragma unroll
            for (int j = 0; j < 4; j++) accO[i][j] *= alpha;

            #pragma unroll
            for (int j = 0; j < 4; j++)
                Ps[(ty * 4 + i) * SPAD + tx * 4 + j] = s[i][j];
        }
        __syncthreads();

        // O += P @ V  (sum over 64 keys)
        for (int kk = 0; kk < AK; kk++) {
            float rp[4], rv[4];
            #pragma unroll
            for (int i = 0; i < 4; i++) rp[i] = Ps[(ty * 4 + i) * SPAD + kk];
            #pragma unroll
            for (int j = 0; j < 4; j++) rv[j] = Vs[kk * SPAD + tx * 4 + j];
            #pragma unroll
            for (int i = 0; i < 4; i++)
                #pragma unroll
                for (int j = 0; j < 4; j++)
                    accO[i][j] = fmaf(rp[i], rv[j], accO[i][j]);
        }
    }

    // Write normalized O into [B*S, D] layout (col = h*64 + d)
    #pragma unroll
    for (int i = 0; i < 4; i++) {
        const float inv_l = 1.0f / l_[i];
        const size_t rowOff = base + (size_t)(q0 + ty * 4 + i) * D_MODEL;
        #pragma unroll
        for (int j = 0; j < 4; j++)
            o[rowOff + tx * 4 + j] = accO[i][j] * inv_l;
    }
}

// ---------------------------------------------------------------------------
// Launch
// ---------------------------------------------------------------------------
extern "C" void kernel_launch(void* const* d_in, const int* in_sizes, int n_in,
                              void* d_out, int out_size) {
    const float* Q  = (const float*)d_in[0];
    const float* K  = (const float*)d_in[1];
    const float* V  = (const float*)d_in[2];
    const float* Wq = (const float*)d_in[3];
    const float* bq = (const float*)d_in[4];
    const float* Wk = (const float*)d_in[5];
    const float* bk = (const float*)d_in[6];
    const float* Wv = (const float*)d_in[7];
    const float* bv = (const float*)d_in[8];
    const float* Wo = (const float*)d_in[9];
    const float* bo = (const float*)d_in[10];
    float* out = (float*)d_out;

    float* dq;    cudaGetSymbolAddress((void**)&dq,    g_q);
    float* dk;    cudaGetSymbolAddress((void**)&dk,    g_k);
    float* dv;    cudaGetSymbolAddress((void**)&dv,    g_v);
    float* dattn; cudaGetSymbolAddress((void**)&dattn, g_attn);

    dim3 gblk(256);
    dim3 ggrid(D_MODEL / BN, M_ROWS / BM);   // (8, 32)

    gemm_bias_kernel<<<ggrid, gblk>>>(Q, Wq, bq, dq, M_ROWS, D_MODEL, D_MODEL);
    gemm_bias_kernel<<<ggrid, gblk>>>(K, Wk, bk, dk, M_ROWS, D_MODEL, D_MODEL);
    gemm_bias_kernel<<<ggrid, gblk>>>(V, Wv, bv, dv, M_ROWS, D_MODEL, D_MODEL);

    cudaFuncSetAttribute(flash_attn_kernel,
                         cudaFuncAttributeMaxDynamicSharedMemorySize, ATTN_SMEM);
    dim3 agrid(SEQ / AQ, BATCH * NUM_HEADS);  // (32, 32)
    flash_attn_kernel<<<agrid, 256, ATTN_SMEM>>>(dq, dk, dv, dattn);

    gemm_bias_kernel<<<ggrid, gblk>>>(dattn, Wo, bo, out, M_ROWS, D_MODEL, D_MODEL);
}

// round 5
// speedup vs baseline: 1.1592x; 1.1592x over previous
#include <cuda_runtime.h>
#include <cuda_bf16.h>
#include <math.h>
#include <stdint.h>

// ---------------------------------------------------------------------------
// Problem constants
// ---------------------------------------------------------------------------
#define D_MODEL   1024
#define NUM_HEADS 16
#define HEAD_DIM  64
#define BATCH     2
#define SEQ       2048
#define M_ROWS    (BATCH * SEQ)      // 4096

// ---------------------------------------------------------------------------
// Scratch (static device globals; no cudaMalloc allowed)
// ---------------------------------------------------------------------------
__device__ float g_q[M_ROWS * D_MODEL];
__device__ float g_k[M_ROWS * D_MODEL];
__device__ float g_v[M_ROWS * D_MODEL];
__device__ float g_attn[M_ROWS * D_MODEL];

// bf16 split operand scratch (reused sequentially across the 4 GEMMs)
__device__ __nv_bfloat16 g_ahi[M_ROWS * D_MODEL];
__device__ __nv_bfloat16 g_alo[M_ROWS * D_MODEL];
__device__ __nv_bfloat16 g_bhi[D_MODEL * D_MODEL];   // W^T  [N,K] K-major
__device__ __nv_bfloat16 g_blo[D_MODEL * D_MODEL];

// ---------------------------------------------------------------------------
// Helpers
// ---------------------------------------------------------------------------
__device__ __forceinline__ uint32_t smem_u32(const void* p) {
    uint32_t a;
    asm("{ .reg .u64 t; cvta.to.shared.u64 t, %1; cvt.u32.u64 %0, t; }"
        : "=r"(a) : "l"(p));
    return a;
}

#define LDSM_X4(r0, r1, r2, r3, addr) \
    asm volatile("ldmatrix.sync.aligned.m8n8.x4.shared.b16 {%0,%1,%2,%3}, [%4];" \
                 : "=r"(r0), "=r"(r1), "=r"(r2), "=r"(r3) : "r"(addr))

#define MMA_BF16(c, a, b) \
    asm volatile("mma.sync.aligned.m16n8k16.row.col.f32.bf16.bf16.f32 " \
                 "{%0,%1,%2,%3}, {%4,%5,%6,%7}, {%8,%9}, {%0,%1,%2,%3};" \
                 : "+f"((c)[0]), "+f"((c)[1]), "+f"((c)[2]), "+f"((c)[3]) \
                 : "r"((a)[0]), "r"((a)[1]), "r"((a)[2]), "r"((a)[3]), \
                   "r"((b)[0]), "r"((b)[1]))

// ---------------------------------------------------------------------------
// fp32 -> bf16 hi/lo split (row-major, for A operands)
// ---------------------------------------------------------------------------
__global__ __launch_bounds__(256)
void split_kernel(const float* __restrict__ in,
                  __nv_bfloat16* __restrict__ hi,
                  __nv_bfloat16* __restrict__ lo, int n4) {
    int i = blockIdx.x * blockDim.x + threadIdx.x;
    if (i >= n4) return;
    float4 v = ((const float4*)in)[i];
    float a[4] = {v.x, v.y, v.z, v.w};
    __nv_bfloat16 h[4], l[4];
#pragma unroll
    for (int j = 0; j < 4; j++) {
        h[j] = __float2bfloat16(a[j]);
        l[j] = __float2bfloat16(a[j] - __bfloat162float(h[j]));
    }
    __nv_bfloat162* h2 = (__nv_bfloat162*)hi;
    __nv_bfloat162* l2 = (__nv_bfloat162*)lo;
    h2[2 * i + 0] = __halves2bfloat162(h[0], h[1]);
    h2[2 * i + 1] = __halves2bfloat162(h[2], h[3]);
    l2[2 * i + 0] = __halves2bfloat162(l[0], l[1]);
    l2[2 * i + 1] = __halves2bfloat162(l[2], l[3]);
}

// ---------------------------------------------------------------------------
// W[K,N] fp32 -> transposed bf16 hi/lo  (Bt[N,K], K-major)
// ---------------------------------------------------------------------------
__global__ __launch_bounds__(1024)
void splitT_kernel(const float* __restrict__ W,
                   __nv_bfloat16* __restrict__ th,
                   __nv_bfloat16* __restrict__ tl) {
    __shared__ float tile[32][33];
    int k = blockIdx.y * 32 + threadIdx.y;
    int n = blockIdx.x * 32 + threadIdx.x;
    tile[threadIdx.y][threadIdx.x] = W[(size_t)k * D_MODEL + n];
    __syncthreads();
    int on = blockIdx.x * 32 + threadIdx.y;
    int ok = blockIdx.y * 32 + threadIdx.x;
    float v = tile[threadIdx.x][threadIdx.y];
    __nv_bfloat16 h = __float2bfloat16(v);
    th[(size_t)on * D_MODEL + ok] = h;
    tl[(size_t)on * D_MODEL + ok] = __float2bfloat16(v - __bfloat162float(h));
}

// ---------------------------------------------------------------------------
// HMMA bf16 split GEMM: C[M,N] = A[M,K] x Bt[N,K]^T + bias
//   (A ~ Ahi+Alo, B ~ Bhi+Blo; compute AhiBhi + AhiBlo + AloBhi in fp32 acc)
// CTA tile 128x128, BK=32, 8 warps (2m x 4n), warp tile 64x32.
// Smem rows padded to 40 bf16 (80B) -> conflict-free ldmatrix.
// ---------------------------------------------------------------------------
#define BKG        32
#define ROWPAD     40                              // bf16 elems per smem row
#define OP_BYTES   (128 * ROWPAD * 2)              // 10240 B per operand tile
#define STAGE_B    (4 * OP_BYTES)                  // Ahi, Alo, Bhi, Blo
#define HG_SMEM    (2 * STAGE_B)                   // 81920 B

__global__ __launch_bounds__(256)
void hgemm_kernel(const __nv_bfloat16* __restrict__ Ahi,
                  const __nv_bfloat16* __restrict__ Alo,
                  const __nv_bfloat16* __restrict__ Bhi,
                  const __nv_bfloat16* __restrict__ Blo,
                  const float* __restrict__ bias,
                  float* __restrict__ C,
                  int M, int N, int K) {
    extern __shared__ char smem[];
    const uint32_t smem_base = smem_u32(smem);

    const int tid = threadIdx.x;
    const int wid = tid >> 5;
    const int lid = tid & 31;
    const int rowBase = blockIdx.y * 128;
    const int colBase = blockIdx.x * 128;
    const int warpM = (wid >> 2) * 64;   // 0 or 64
    const int warpN = (wid & 3) * 32;    // 0,32,64,96

    // Global source bases for this CTA
    const __nv_bfloat16* gsrc0 = Ahi + (size_t)rowBase * K;
    const __nv_bfloat16* gsrc1 = Alo + (size_t)rowBase * K;
    const __nv_bfloat16* gsrc2 = Bhi + (size_t)colBase * K;
    const __nv_bfloat16* gsrc3 = Blo + (size_t)colBase * K;

    // Loader mapping: per operand, 128 rows x 32 cols = 512 uint4; 2/thread.
    const int ldRow0 = tid >> 2;          // 0..63
    const int ldCol  = (tid & 3) * 8;     // 0,8,16,24

    // ldmatrix lane address components
    //  A: lanes 0-15 -> rows (l&15), k+0; lanes 16-31 -> same rows, k+8
    const int aLaneRow = lid & 15;
    const int aLaneK   = (lid >> 4) * 8;
    //  B: lanes (l&7)+((l>>4)<<3) -> n rows; ((l>>3)&1)*8 -> k offset
    const int bLaneRow = (lid & 7) + ((lid >> 4) << 3);
    const int bLaneK   = ((lid >> 3) & 1) * 8;

    float acc[4][4][4];   // [mb][nb][c0..c3]
#pragma unroll
    for (int i = 0; i < 4; i++)
#pragma unroll
        for (int j = 0; j < 4; j++)
#pragma unroll
            for (int c = 0; c < 4; c++) acc[i][j][c] = 0.0f;

    const int NIT = K / BKG;   // 32
    uint4 ldreg[8];

    // ---- prologue: load tile 0 into stage 0 ----
#pragma unroll
    for (int op = 0; op < 4; op++) {
        const __nv_bfloat16* src =
            (op == 0) ? gsrc0 : (op == 1) ? gsrc1 : (op == 2) ? gsrc2 : gsrc3;
#pragma unroll
        for (int h = 0; h < 2; h++) {
            int r = ldRow0 + h * 64;
            uint4 v = *(const uint4*)(src + (size_t)r * K + ldCol);
            *(uint4*)(smem + op * OP_BYTES + r * (ROWPAD * 2) + ldCol * 2) = v;
        }
    }
    __syncthreads();

    for (int it = 0; it < NIT; it++) {
        const int s = it & 1;
        const uint32_t stage = smem_base + s * STAGE_B;

        // ---- issue global loads for next tile ----
        if (it + 1 < NIT) {
            const int k0 = (it + 1) * BKG;
#pragma unroll
            for (int op = 0; op < 4; op++) {
                const __nv_bfloat16* src =
                    (op == 0) ? gsrc0 : (op == 1) ? gsrc1 : (op == 2) ? gsrc2 : gsrc3;
#pragma unroll
                for (int h = 0; h < 2; h++) {
                    int r = ldRow0 + h * 64;
                    ldreg[op * 2 + h] = *(const uint4*)(src + (size_t)r * K + k0 + ldCol);
                }
            }
        }

        // ---- compute on stage s ----
        const uint32_t aHiBase = stage + 0 * OP_BYTES +
                                 (warpM + aLaneRow) * (ROWPAD * 2) + aLaneK * 2;
        const uint32_t aLoBase = aHiBase + OP_BYTES;
        const uint32_t bHiBase = stage + 2 * OP_BYTES +
                                 (warpN + bLaneRow) * (ROWPAD * 2) + bLaneK * 2;
        const uint32_t bLoBase = bHiBase + OP_BYTES;

#pragma unroll
        for (int ks = 0; ks < 2; ks++) {
            const uint32_t koff = ks * 32;   // 16 bf16 = 32 bytes

            uint32_t ah[4][4], al[4][4];
#pragma unroll
            for (int mb = 0; mb < 4; mb++) {
                LDSM_X4(ah[mb][0], ah[mb][1], ah[mb][2], ah[mb][3],
                        aHiBase + mb * 16 * (ROWPAD * 2) + koff);
                LDSM_X4(al[mb][0], al[mb][1], al[mb][2], al[mb][3],
                        aLoBase + mb * 16 * (ROWPAD * 2) + koff);
            }
            uint32_t bh[4][2], bl[4][2];
#pragma unroll
            for (int np = 0; np < 2; np++) {
                uint32_t r0, r1, r2, r3;
                LDSM_X4(r0, r1, r2, r3,
                        bHiBase + np * 16 * (ROWPAD * 2) + koff);
                bh[np * 2 + 0][0] = r0; bh[np * 2 + 0][1] = r1;
                bh[np * 2 + 1][0] = r2; bh[np * 2 + 1][1] = r3;
                LDSM_X4(r0, r1, r2, r3,
                        bLoBase + np * 16 * (ROWPAD * 2) + koff);
                bl[np * 2 + 0][0] = r0; bl[np * 2 + 0][1] = r1;
                bl[np * 2 + 1][0] = r2; bl[np * 2 + 1][1] = r3;
            }

#pragma unroll
            for (int mb = 0; mb < 4; mb++)
#pragma unroll
                for (int nb = 0; nb < 4; nb++) {
                    MMA_BF16(acc[mb][nb], ah[mb], bh[nb]);
                    MMA_BF16(acc[mb][nb], ah[mb], bl[nb]);
                    MMA_BF16(acc[mb][nb], al[mb], bh[nb]);
                }
        }

        // ---- store next tile into other stage ----
        if (it + 1 < NIT) {
            char* nstage = smem + (s ^ 1) * STAGE_B;
#pragma unroll
            for (int op = 0; op < 4; op++)
#pragma unroll
                for (int h = 0; h < 2; h++) {
                    int r = ldRow0 + h * 64;
                    *(uint4*)(nstage + op * OP_BYTES + r * (ROWPAD * 2) + ldCol * 2) =
                        ldreg[op * 2 + h];
                }
            __syncthreads();
        }
    }

    // ---- epilogue: bias add + store ----
    const int gid = lid >> 2;
    const int tig = lid & 3;
#pragma unroll
    for (int mb = 0; mb < 4; mb++) {
#pragma unroll
        for (int nb = 0; nb < 4; nb++) {
            const int col = colBase + warpN + nb * 8 + tig * 2;
            const float2 bv = *(const float2*)(bias + col);
            const int r0 = rowBase + warpM + mb * 16 + gid;
            float2 v0, v1;
            v0.x = acc[mb][nb][0] + bv.x;
            v0.y = acc[mb][nb][1] + bv.y;
            v1.x = acc[mb][nb][2] + bv.x;
            v1.y = acc[mb][nb][3] + bv.y;
            *(float2*)(C + (size_t)r0 * N + col) = v0;
            *(float2*)(C + (size_t)(r0 + 8) * N + col) = v1;
        }
    }
}

// ---------------------------------------------------------------------------
// Flash attention (fp32 streaming softmax) — unchanged
// ---------------------------------------------------------------------------
#define AQ   64
#define AK   64
#define SPAD 68
#define ATTN_SMEM (4 * AQ * SPAD * 4)

__global__ __launch_bounds__(256)
void flash_attn_kernel(const float* __restrict__ q,
                       const float* __restrict__ k,
                       const float* __restrict__ v,
                       float* __restrict__ o) {
    extern __shared__ float sm[];
    float* Qs = sm;
    float* Ks = Qs + AQ * SPAD;
    float* Vs = Ks + AK * SPAD;
    float* Ps = Vs + AK * SPAD;

    const int tid = threadIdx.x;
    const int tx  = tid % 16;
    const int ty  = tid / 16;
    const int bh  = blockIdx.y;
    const int b   = bh / NUM_HEADS;
    const int h   = bh % NUM_HEADS;
    const int q0  = blockIdx.x * AQ;

    const size_t base = (size_t)b * SEQ * D_MODEL + (size_t)h * HEAD_DIM;
    const float qscale = 0.125f;   // 1/sqrt(64)

    for (int idx = tid; idx < AQ * HEAD_DIM / 4; idx += 256) {
        int r  = idx / 16;
        int c4 = (idx % 16) * 4;
        float4 vq = *(const float4*)(q + base + (size_t)(q0 + r) * D_MODEL + c4);
        Qs[r * SPAD + c4 + 0] = vq.x * qscale;
        Qs[r * SPAD + c4 + 1] = vq.y * qscale;
        Qs[r * SPAD + c4 + 2] = vq.z * qscale;
        Qs[r * SPAD + c4 + 3] = vq.w * qscale;
    }

    float m_[4], l_[4], accO[4][4];
#pragma unroll
    for (int i = 0; i < 4; i++) {
        m_[i] = -INFINITY;
        l_[i] = 0.0f;
#pragma unroll
        for (int j = 0; j < 4; j++) accO[i][j] = 0.0f;
    }

    for (int kt = 0; kt < SEQ / AK; kt++) {
        __syncthreads();

        const int k0r = kt * AK;
        for (int idx = tid; idx < AK * HEAD_DIM / 4; idx += 256) {
            int r  = idx / 16;
            int c4 = (idx % 16) * 4;
            float4 vk = *(const float4*)(k + base + (size_t)(k0r + r) * D_MODEL + c4);
            Ks[r * SPAD + c4 + 0] = vk.x;
            Ks[r * SPAD + c4 + 1] = vk.y;
            Ks[r * SPAD + c4 + 2] = vk.z;
            Ks[r * SPAD + c4 + 3] = vk.w;
            float4 vv = *(const float4*)(v + base + (size_t)(k0r + r) * D_MODEL + c4);
            Vs[r * SPAD + c4 + 0] = vv.x;
            Vs[r * SPAD + c4 + 1] = vv.y;
            Vs[r * SPAD + c4 + 2] = vv.z;
            Vs[r * SPAD + c4 + 3] = vv.w;
        }
        __syncthreads();

        float s[4][4];
#pragma unroll
        for (int i = 0; i < 4; i++)
#pragma unroll
            for (int j = 0; j < 4; j++) s[i][j] = 0.0f;

        for (int d = 0; d < HEAD_DIM; d++) {
            float ra[4], rb[4];
#pragma unroll
            for (int i = 0; i < 4; i++) ra[i] = Qs[(ty * 4 + i) * SPAD + d];
#pragma unroll
            for (int j = 0; j < 4; j++) rb[j] = Ks[(tx * 4 + j) * SPAD + d];
#pragma unroll
            for (int i = 0; i < 4; i++)
#pragma unroll
                for (int j = 0; j < 4; j++)
                    s[i][j] = fmaf(ra[i], rb[j], s[i][j]);
        }

#pragma unroll
        for (int i = 0; i < 4; i++) {
            float mt = s[i][0];
#pragma unroll
            for (int j = 1; j < 4; j++) mt = fmaxf(mt, s[i][j]);
#pragma unroll
            for (int off = 8; off > 0; off >>= 1)
                mt = fmaxf(mt, __shfl_xor_sync(0xffffffffu, mt, off));

            float mnew  = fmaxf(m_[i], mt);
            float alpha = __expf(m_[i] - mnew);

            float lsum = 0.0f;
#pragma unroll
            for (int j = 0; j < 4; j++) {
                s[i][j] = __expf(s[i][j] - mnew);
                lsum += s[i][j];
            }
#pragma unroll
            for (int off = 8; off > 0; off >>= 1)
                lsum += __shfl_xor_sync(0xffffffffu, lsum, off);

            l_[i] = l_[i] * alpha + lsum;
            m_[i] = mnew;

#pragma unroll
            for (int j = 0; j < 4; j++) accO[i][j] *= alpha;

#pragma unroll
            for (int j = 0; j < 4; j++)
                Ps[(ty * 4 + i) * SPAD + tx * 4 + j] = s[i][j];
        }
        __syncthreads();

        for (int kk = 0; kk < AK; kk++) {
            float rp[4], rv[4];
#pragma unroll
            for (int i = 0; i < 4; i++) rp[i] = Ps[(ty * 4 + i) * SPAD + kk];
#pragma unroll
            for (int j = 0; j < 4; j++) rv[j] = Vs[kk * SPAD + tx * 4 + j];
#pragma unroll
            for (int i = 0; i < 4; i++)
#pragma unroll
                for (int j = 0; j < 4; j++)
                    accO[i][j] = fmaf(rp[i], rv[j], accO[i][j]);
        }
    }

#pragma unroll
    for (int i = 0; i < 4; i++) {
        const float inv_l = 1.0f / l_[i];
        const size_t rowOff = base + (size_t)(q0 + ty * 4 + i) * D_MODEL;
#pragma unroll
        for (int j = 0; j < 4; j++)
            o[rowOff + tx * 4 + j] = accO[i][j] * inv_l;
    }
}

// ---------------------------------------------------------------------------
// Launch
// ---------------------------------------------------------------------------
static void run_tensor_gemm(const float* A, const float* W, const float* bias,
                            float* C,
                            __nv_bfloat16* ahi, __nv_bfloat16* alo,
                            __nv_bfloat16* bhi, __nv_bfloat16* blo) {
    split_kernel<<<(M_ROWS * D_MODEL / 4 + 255) / 256, 256>>>(A, ahi, alo,
                                                              M_ROWS * D_MODEL / 4);
    splitT_kernel<<<dim3(32, 32), dim3(32, 32)>>>(W, bhi, blo);
    dim3 grid(D_MODEL / 128, M_ROWS / 128);   // (8, 32)
    hgemm_kernel<<<grid, 256, HG_SMEM>>>(ahi, alo, bhi, blo, bias, C,
                                         M_ROWS, D_MODEL, D_MODEL);
}

extern "C" void kernel_launch(void* const* d_in, const int* in_sizes, int n_in,
                              void* d_out, int out_size) {
    const float* Q  = (const float*)d_in[0];
    const float* K  = (const float*)d_in[1];
    const float* V  = (const float*)d_in[2];
    const float* Wq = (const float*)d_in[3];
    const float* bq = (const float*)d_in[4];
    const float* Wk = (const float*)d_in[5];
    const float* bk = (const float*)d_in[6];
    const float* Wv = (const float*)d_in[7];
    const float* bv = (const float*)d_in[8];
    const float* Wo = (const float*)d_in[9];
    const float* bo = (const float*)d_in[10];
    float* out = (float*)d_out;

    float* dq;    cudaGetSymbolAddress((void**)&dq,    g_q);
    float* dk;    cudaGetSymbolAddress((void**)&dk,    g_k);
    float* dv;    cudaGetSymbolAddress((void**)&dv,    g_v);
    float* dattn; cudaGetSymbolAddress((void**)&dattn, g_attn);
    __nv_bfloat16* ahi; cudaGetSymbolAddress((void**)&ahi, g_ahi);
    __nv_bfloat16* alo; cudaGetSymbolAddress((void**)&alo, g_alo);
    __nv_bfloat16* bhi; cudaGetSymbolAddress((void**)&bhi, g_bhi);
    __nv_bfloat16* blo; cudaGetSymbolAddress((void**)&blo, g_blo);

    cudaFuncSetAttribute(hgemm_kernel,
                         cudaFuncAttributeMaxDynamicSharedMemorySize, HG_SMEM);
    cudaFuncSetAttribute(flash_attn_kernel,
                         cudaFuncAttributeMaxDynamicSharedMemorySize, ATTN_SMEM);

    run_tensor_gemm(Q, Wq, bq, dq, ahi, alo, bhi, blo);
    run_tensor_gemm(K, Wk, bk, dk, ahi, alo, bhi, blo);
    run_tensor_gemm(V, Wv, bv, dv, ahi, alo, bhi, blo);

    dim3 agrid(SEQ / AQ, BATCH * NUM_HEADS);  // (32, 32)
    flash_attn_kernel<<<agrid, 256, ATTN_SMEM>>>(dq, dk, dv, dattn);

    run_tensor_gemm(dattn, Wo, bo, out, ahi, alo, bhi, blo);
}

// round 6
// speedup vs baseline: 3.8508x; 3.3221x over previous
#include <cuda_runtime.h>
#include <cuda_bf16.h>
#include <math.h>
#include <stdint.h>

// ---------------------------------------------------------------------------
// Problem constants
// ---------------------------------------------------------------------------
#define D_MODEL   1024
#define NUM_HEADS 16
#define HEAD_DIM  64
#define BATCH     2
#define SEQ       2048
#define M_ROWS    (BATCH * SEQ)      // 4096

// ---------------------------------------------------------------------------
// Scratch (static device globals; no cudaMalloc allowed)
// ---------------------------------------------------------------------------
__device__ float g_q[M_ROWS * D_MODEL];
__device__ float g_k[M_ROWS * D_MODEL];
__device__ float g_v[M_ROWS * D_MODEL];
__device__ float g_attn[M_ROWS * D_MODEL];

// bf16 split operand scratch for the dense GEMMs
__device__ __nv_bfloat16 g_ahi[M_ROWS * D_MODEL];
__device__ __nv_bfloat16 g_alo[M_ROWS * D_MODEL];
__device__ __nv_bfloat16 g_bhi[D_MODEL * D_MODEL];   // W^T  [N,K] K-major
__device__ __nv_bfloat16 g_blo[D_MODEL * D_MODEL];

// attention pre-split operands
__device__ __nv_bfloat16 g_qhi[M_ROWS * D_MODEL];    // [B,H,S,64], prescaled
__device__ __nv_bfloat16 g_qlo[M_ROWS * D_MODEL];
__device__ __nv_bfloat16 g_khi[M_ROWS * D_MODEL];    // [B,H,S,64]
__device__ __nv_bfloat16 g_klo[M_ROWS * D_MODEL];
__device__ __nv_bfloat16 g_vthi[M_ROWS * D_MODEL];   // [B,H,64,S]
__device__ __nv_bfloat16 g_vtlo[M_ROWS * D_MODEL];

// ---------------------------------------------------------------------------
// Helpers
// ---------------------------------------------------------------------------
__device__ __forceinline__ uint32_t smem_u32(const void* p) {
    uint32_t a;
    asm("{ .reg .u64 t; cvta.to.shared.u64 t, %1; cvt.u32.u64 %0, t; }"
        : "=r"(a) : "l"(p));
    return a;
}

#define LDSM_X4(r0, r1, r2, r3, addr) \
    asm volatile("ldmatrix.sync.aligned.m8n8.x4.shared.b16 {%0,%1,%2,%3}, [%4];" \
                 : "=r"(r0), "=r"(r1), "=r"(r2), "=r"(r3) : "r"(addr))

#define MMA_BF16(c, a, b) \
    asm volatile("mma.sync.aligned.m16n8k16.row.col.f32.bf16.bf16.f32 " \
                 "{%0,%1,%2,%3}, {%4,%5,%6,%7}, {%8,%9}, {%0,%1,%2,%3};" \
                 : "+f"((c)[0]), "+f"((c)[1]), "+f"((c)[2]), "+f"((c)[3]) \
                 : "r"((a)[0]), "r"((a)[1]), "r"((a)[2]), "r"((a)[3]), \
                   "r"((b)[0]), "r"((b)[1]))

__device__ __forceinline__ uint32_t packbf(float hi, float lo) {
    uint32_t r;
    asm("cvt.rn.bf16x2.f32 %0, %1, %2;" : "=r"(r) : "f"(hi), "f"(lo));
    return r;
}
__device__ __forceinline__ float bf_lo(uint32_t h) { return __int_as_float(h << 16); }
__device__ __forceinline__ float bf_hi(uint32_t h) { return __int_as_float(h & 0xffff0000u); }

// Fast e^x via 2^f polynomial (deg-6 Taylor) + exponent bit-trick.
// Valid for x <= 0 (clamped at -80); rel err ~1.5e-5. Avoids MUFU.
__device__ __forceinline__ float fexp(float x) {
    x = fmaxf(x, -80.0f);
    float t = x * 1.4426950408889634f;
    float n = floorf(t);
    float f = t - n;
    float p = 1.5403530393e-4f;
    p = fmaf(p, f, 1.3333558146e-3f);
    p = fmaf(p, f, 9.6181291076e-3f);
    p = fmaf(p, f, 5.5504108665e-2f);
    p = fmaf(p, f, 2.4022650696e-1f);
    p = fmaf(p, f, 6.9314718056e-1f);
    p = fmaf(p, f, 1.0f);
    return __int_as_float(__float_as_int(p) + (((int)n) << 23));
}

// ---------------------------------------------------------------------------
// fp32 -> bf16 hi/lo split (row-major, for GEMM A operands)
// ---------------------------------------------------------------------------
__global__ __launch_bounds__(256)
void split_kernel(const float* __restrict__ in,
                  __nv_bfloat16* __restrict__ hi,
                  __nv_bfloat16* __restrict__ lo, int n4) {
    int i = blockIdx.x * blockDim.x + threadIdx.x;
    if (i >= n4) return;
    float4 v = ((const float4*)in)[i];
    float a[4] = {v.x, v.y, v.z, v.w};
    __nv_bfloat16 h[4], l[4];
#pragma unroll
    for (int j = 0; j < 4; j++) {
        h[j] = __float2bfloat16(a[j]);
        l[j] = __float2bfloat16(a[j] - __bfloat162float(h[j]));
    }
    __nv_bfloat162* h2 = (__nv_bfloat162*)hi;
    __nv_bfloat162* l2 = (__nv_bfloat162*)lo;
    h2[2 * i + 0] = __halves2bfloat162(h[0], h[1]);
    h2[2 * i + 1] = __halves2bfloat162(h[2], h[3]);
    l2[2 * i + 0] = __halves2bfloat162(l[0], l[1]);
    l2[2 * i + 1] = __halves2bfloat162(l[2], l[3]);
}

// ---------------------------------------------------------------------------
// W[K,N] fp32 -> transposed bf16 hi/lo  (Bt[N,K], K-major)
// ---------------------------------------------------------------------------
__global__ __launch_bounds__(1024)
void splitT_kernel(const float* __restrict__ W,
                   __nv_bfloat16* __restrict__ th,
                   __nv_bfloat16* __restrict__ tl) {
    __shared__ float tile[32][33];
    int k = blockIdx.y * 32 + threadIdx.y;
    int n = blockIdx.x * 32 + threadIdx.x;
    tile[threadIdx.y][threadIdx.x] = W[(size_t)k * D_MODEL + n];
    __syncthreads();
    int on = blockIdx.x * 32 + threadIdx.y;
    int ok = blockIdx.y * 32 + threadIdx.x;
    float v = tile[threadIdx.x][threadIdx.y];
    __nv_bfloat16 h = __float2bfloat16(v);
    th[(size_t)on * D_MODEL + ok] = h;
    tl[(size_t)on * D_MODEL + ok] = __float2bfloat16(v - __bfloat162float(h));
}

// ---------------------------------------------------------------------------
// Head-major split: fp32 [B,S,D] -> bf16 hi/lo [B,H,S,64], optional scale
// ---------------------------------------------------------------------------
__global__ __launch_bounds__(256)
void split_head_kernel(const float* __restrict__ src,
                       __nv_bfloat16* __restrict__ hi,
                       __nv_bfloat16* __restrict__ lo, float scale) {
    int t = blockIdx.x * blockDim.x + threadIdx.x;   // 1M threads, 4 elems each
    if (t >= M_ROWS * D_MODEL / 4) return;
    int d4 = t & 15;
    int s  = (t >> 4) & (SEQ - 1);
    int bh = t >> 15;
    int b = bh >> 4, h = bh & 15;
    float4 v = *(const float4*)(src + ((size_t)b * SEQ + s) * D_MODEL + h * 64 + d4 * 4);
    float a[4] = {v.x * scale, v.y * scale, v.z * scale, v.w * scale};
    __nv_bfloat16 hh[4], ll[4];
#pragma unroll
    for (int j = 0; j < 4; j++) {
        hh[j] = __float2bfloat16(a[j]);
        ll[j] = __float2bfloat16(a[j] - __bfloat162float(hh[j]));
    }
    __nv_bfloat162* h2 = (__nv_bfloat162*)(hi + (size_t)t * 4);
    __nv_bfloat162* l2 = (__nv_bfloat162*)(lo + (size_t)t * 4);
    h2[0] = __halves2bfloat162(hh[0], hh[1]);
    h2[1] = __halves2bfloat162(hh[2], hh[3]);
    l2[0] = __halves2bfloat162(ll[0], ll[1]);
    l2[1] = __halves2bfloat162(ll[2], ll[3]);
}

// ---------------------------------------------------------------------------
// V transpose split: fp32 [B,S,D] -> bf16 hi/lo [B,H,64,S]
// ---------------------------------------------------------------------------
__global__ __launch_bounds__(256)
void split_vt_kernel(const float* __restrict__ v,
                     __nv_bfloat16* __restrict__ hi,
                     __nv_bfloat16* __restrict__ lo) {
    __shared__ float tile[64][65];
    const int s0 = blockIdx.x * 64;
    const int bh = blockIdx.y;
    const int b = bh >> 4, h = bh & 15;
    for (int i = threadIdx.x; i < 64 * 16; i += 256) {
        int r = i >> 4, c4 = i & 15;
        float4 vv = *(const float4*)(v + ((size_t)b * SEQ + s0 + r) * D_MODEL + h * 64 + c4 * 4);
        tile[r][c4 * 4 + 0] = vv.x;
        tile[r][c4 * 4 + 1] = vv.y;
        tile[r][c4 * 4 + 2] = vv.z;
        tile[r][c4 * 4 + 3] = vv.w;
    }
    __syncthreads();
    for (int i = threadIdx.x; i < 64 * 32; i += 256) {
        int d = i >> 5, c2 = i & 31;
        float a0 = tile[c2 * 2 + 0][d];
        float a1 = tile[c2 * 2 + 1][d];
        __nv_bfloat16 h0 = __float2bfloat16(a0);
        __nv_bfloat16 h1 = __float2bfloat16(a1);
        __nv_bfloat16 l0 = __float2bfloat16(a0 - __bfloat162float(h0));
        __nv_bfloat16 l1 = __float2bfloat16(a1 - __bfloat162float(h1));
        size_t off = (size_t)bh * 64 * SEQ + (size_t)d * SEQ + s0 + c2 * 2;
        *(__nv_bfloat162*)(hi + off) = __halves2bfloat162(h0, h1);
        *(__nv_bfloat162*)(lo + off) = __halves2bfloat162(l0, l1);
    }
}

// ---------------------------------------------------------------------------
// HMMA bf16 split GEMM (unchanged from round 5; passing)
// ---------------------------------------------------------------------------
#define BKG        32
#define ROWPAD     40
#define OP_BYTES   (128 * ROWPAD * 2)
#define STAGE_B    (4 * OP_BYTES)
#define HG_SMEM    (2 * STAGE_B)

__global__ __launch_bounds__(256)
void hgemm_kernel(const __nv_bfloat16* __restrict__ Ahi,
                  const __nv_bfloat16* __restrict__ Alo,
                  const __nv_bfloat16* __restrict__ Bhi,
                  const __nv_bfloat16* __restrict__ Blo,
                  const float* __restrict__ bias,
                  float* __restrict__ C,
                  int M, int N, int K) {
    extern __shared__ char smem[];
    const uint32_t smem_base = smem_u32(smem);

    const int tid = threadIdx.x;
    const int wid = tid >> 5;
    const int lid = tid & 31;
    const int rowBase = blockIdx.y * 128;
    const int colBase = blockIdx.x * 128;
    const int warpM = (wid >> 2) * 64;
    const int warpN = (wid & 3) * 32;

    const __nv_bfloat16* gsrc0 = Ahi + (size_t)rowBase * K;
    const __nv_bfloat16* gsrc1 = Alo + (size_t)rowBase * K;
    const __nv_bfloat16* gsrc2 = Bhi + (size_t)colBase * K;
    const __nv_bfloat16* gsrc3 = Blo + (size_t)colBase * K;

    const int ldRow0 = tid >> 2;
    const int ldCol  = (tid & 3) * 8;

    const int aLaneRow = lid & 15;
    const int aLaneK   = (lid >> 4) * 8;
    const int bLaneRow = (lid & 7) + ((lid >> 4) << 3);
    const int bLaneK   = ((lid >> 3) & 1) * 8;

    float acc[4][4][4];
#pragma unroll
    for (int i = 0; i < 4; i++)
#pragma unroll
        for (int j = 0; j < 4; j++)
#pragma unroll
            for (int c = 0; c < 4; c++) acc[i][j][c] = 0.0f;

    const int NIT = K / BKG;
    uint4 ldreg[8];

#pragma unroll
    for (int op = 0; op < 4; op++) {
        const __nv_bfloat16* src =
            (op == 0) ? gsrc0 : (op == 1) ? gsrc1 : (op == 2) ? gsrc2 : gsrc3;
#pragma unroll
        for (int h = 0; h < 2; h++) {
            int r = ldRow0 + h * 64;
            uint4 v = *(const uint4*)(src + (size_t)r * K + ldCol);
            *(uint4*)(smem + op * OP_BYTES + r * (ROWPAD * 2) + ldCol * 2) = v;
        }
    }
    __syncthreads();

    for (int it = 0; it < NIT; it++) {
        const int s = it & 1;
        const uint32_t stage = smem_base + s * STAGE_B;

        if (it + 1 < NIT) {
            const int k0 = (it + 1) * BKG;
#pragma unroll
            for (int op = 0; op < 4; op++) {
                const __nv_bfloat16* src =
                    (op == 0) ? gsrc0 : (op == 1) ? gsrc1 : (op == 2) ? gsrc2 : gsrc3;
#pragma unroll
                for (int h = 0; h < 2; h++) {
                    int r = ldRow0 + h * 64;
                    ldreg[op * 2 + h] = *(const uint4*)(src + (size_t)r * K + k0 + ldCol);
                }
            }
        }

        const uint32_t aHiBase = stage + 0 * OP_BYTES +
                                 (warpM + aLaneRow) * (ROWPAD * 2) + aLaneK * 2;
        const uint32_t aLoBase = aHiBase + OP_BYTES;
        const uint32_t bHiBase = stage + 2 * OP_BYTES +
                                 (warpN + bLaneRow) * (ROWPAD * 2) + bLaneK * 2;
        const uint32_t bLoBase = bHiBase + OP_BYTES;

#pragma unroll
        for (int ks = 0; ks < 2; ks++) {
            const uint32_t koff = ks * 32;

            uint32_t ah[4][4], al[4][4];
#pragma unroll
            for (int mb = 0; mb < 4; mb++) {
                LDSM_X4(ah[mb][0], ah[mb][1], ah[mb][2], ah[mb][3],
                        aHiBase + mb * 16 * (ROWPAD * 2) + koff);
                LDSM_X4(al[mb][0], al[mb][1], al[mb][2], al[mb][3],
                        aLoBase + mb * 16 * (ROWPAD * 2) + koff);
            }
            uint32_t bh[4][2], bl[4][2];
#pragma unroll
            for (int np = 0; np < 2; np++) {
                uint32_t r0, r1, r2, r3;
                LDSM_X4(r0, r1, r2, r3, bHiBase + np * 16 * (ROWPAD * 2) + koff);
                bh[np * 2 + 0][0] = r0; bh[np * 2 + 0][1] = r1;
                bh[np * 2 + 1][0] = r2; bh[np * 2 + 1][1] = r3;
                LDSM_X4(r0, r1, r2, r3, bLoBase + np * 16 * (ROWPAD * 2) + koff);
                bl[np * 2 + 0][0] = r0; bl[np * 2 + 0][1] = r1;
                bl[np * 2 + 1][0] = r2; bl[np * 2 + 1][1] = r3;
            }

#pragma unroll
            for (int mb = 0; mb < 4; mb++)
#pragma unroll
                for (int nb = 0; nb < 4; nb++) {
                    MMA_BF16(acc[mb][nb], ah[mb], bh[nb]);
                    MMA_BF16(acc[mb][nb], ah[mb], bl[nb]);
                    MMA_BF16(acc[mb][nb], al[mb], bh[nb]);
                }
        }

        if (it + 1 < NIT) {
            char* nstage = smem + (s ^ 1) * STAGE_B;
#pragma unroll
            for (int op = 0; op < 4; op++)
#pragma unroll
                for (int h = 0; h < 2; h++) {
                    int r = ldRow0 + h * 64;
                    *(uint4*)(nstage + op * OP_BYTES + r * (ROWPAD * 2) + ldCol * 2) =
                        ldreg[op * 2 + h];
                }
            __syncthreads();
        }
    }

    const int gid = lid >> 2;
    const int tig = lid & 3;
#pragma unroll
    for (int mb = 0; mb < 4; mb++) {
#pragma unroll
        for (int nb = 0; nb < 4; nb++) {
            const int col = colBase + warpN + nb * 8 + tig * 2;
            const float2 bv = *(const float2*)(bias + col);
            const int r0 = rowBase + warpM + mb * 16 + gid;
            float2 v0, v1;
            v0.x = acc[mb][nb][0] + bv.x;
            v0.y = acc[mb][nb][1] + bv.y;
            v1.x = acc[mb][nb][2] + bv.x;
            v1.y = acc[mb][nb][3] + bv.y;
            *(float2*)(C + (size_t)r0 * N + col) = v0;
            *(float2*)(C + (size_t)(r0 + 8) * N + col) = v1;
        }
    }
}

// ---------------------------------------------------------------------------
// HMMA flash attention.
// CTA: 128 queries of one (b,h), 8 warps x 16 query rows, key tile 64.
// Q (prescaled) kept as A-fragments in registers; K as B-frags (n=keys,k=dh);
// V^T as B-frags (n=dh, k=keys). P stays in registers (C-frag == A-frag).
// 3-term hi/lo splits on both MMAs; polynomial exp.
// ---------------------------------------------------------------------------
#define KVP_B   144                        // smem row stride bytes (72 bf16)
#define QHI_B   0
#define QLO_B   18432
#define KHI_B   36864
#define KLO_B   46080
#define VHI_B   55296
#define VLO_B   64512
#define FA_SMEM 73728

__global__ __launch_bounds__(256, 1)
void flash_hmma_kernel(const __nv_bfloat16* __restrict__ qhi,
                       const __nv_bfloat16* __restrict__ qlo,
                       const __nv_bfloat16* __restrict__ khi,
                       const __nv_bfloat16* __restrict__ klo,
                       const __nv_bfloat16* __restrict__ vthi,
                       const __nv_bfloat16* __restrict__ vtlo,
                       float* __restrict__ o) {
    extern __shared__ char smc[];
    const uint32_t smb = smem_u32(smc);

    const int tid = threadIdx.x;
    const int wid = tid >> 5;
    const int lid = tid & 31;
    const int bh = blockIdx.y;
    const int b = bh >> 4, h = bh & 15;
    const int q0 = blockIdx.x * 128;

    const size_t qbase = ((size_t)bh * SEQ + q0) * 64;
    const size_t kbase = (size_t)bh * SEQ * 64;
    const size_t vbase = (size_t)bh * 64 * SEQ;

    // ---- load Q tile (hi/lo), 128 rows x 64 bf16 each ----
#pragma unroll
    for (int i = 0; i < 4; i++) {
        int e = tid + i * 256;
        int r = e >> 3, c = e & 7;
        *(uint4*)(smc + QHI_B + r * KVP_B + c * 16) =
            *(const uint4*)(qhi + qbase + (size_t)r * 64 + c * 8);
        *(uint4*)(smc + QLO_B + r * KVP_B + c * 16) =
            *(const uint4*)(qlo + qbase + (size_t)r * 64 + c * 8);
    }
    __syncthreads();

    // ---- Q fragments (held in registers for whole kernel) ----
    const int warpQ = wid * 16;
    const int aRow = lid & 15;
    const int aK   = (lid >> 4) * 8;
    uint32_t qh_[4][4], ql_[4][4];
#pragma unroll
    for (int kk = 0; kk < 4; kk++) {
        uint32_t addr = smb + QHI_B + (warpQ + aRow) * KVP_B + (aK + kk * 16) * 2;
        LDSM_X4(qh_[kk][0], qh_[kk][1], qh_[kk][2], qh_[kk][3], addr);
        LDSM_X4(ql_[kk][0], ql_[kk][1], ql_[kk][2], ql_[kk][3],
                addr + (QLO_B - QHI_B));
    }

    float O_[8][4];
#pragma unroll
    for (int j = 0; j < 8; j++)
#pragma unroll
        for (int c = 0; c < 4; c++) O_[j][c] = 0.0f;
    float m0 = -1e30f, m1 = -1e30f, l0 = 0.0f, l1 = 0.0f;

    const int bRow = (lid & 7) + ((lid >> 4) << 3);
    const int bK   = ((lid >> 3) & 1) * 8;

    for (int kt = 0; kt < SEQ / 64; kt++) {
        const int k0 = kt * 64;

        // ---- load K and V^T tiles (hi/lo) ----
#pragma unroll
        for (int i = 0; i < 2; i++) {
            int e = tid + i * 256;
            int r = e >> 3, c = e & 7;
            *(uint4*)(smc + KHI_B + r * KVP_B + c * 16) =
                *(const uint4*)(khi + kbase + (size_t)(k0 + r) * 64 + c * 8);
            *(uint4*)(smc + KLO_B + r * KVP_B + c * 16) =
                *(const uint4*)(klo + kbase + (size_t)(k0 + r) * 64 + c * 8);
            *(uint4*)(smc + VHI_B + r * KVP_B + c * 16) =
                *(const uint4*)(vthi + vbase + (size_t)r * SEQ + k0 + c * 8);
            *(uint4*)(smc + VLO_B + r * KVP_B + c * 16) =
                *(const uint4*)(vtlo + vbase + (size_t)r * SEQ + k0 + c * 8);
        }
        __syncthreads();

        // ---- S = Q K^T (16q x 64keys per warp), 3-term split ----
        float S_[8][4];
#pragma unroll
        for (int j = 0; j < 8; j++)
#pragma unroll
            for (int c = 0; c < 4; c++) S_[j][c] = 0.0f;

#pragma unroll
        for (int kk = 0; kk < 4; kk++) {
            uint32_t kbh[8][2], kbl[8][2];
#pragma unroll
            for (int np = 0; np < 4; np++) {
                uint32_t r0, r1, r2, r3;
                uint32_t addr = smb + KHI_B + (np * 16 + bRow) * KVP_B +
                                (bK + kk * 16) * 2;
                LDSM_X4(r0, r1, r2, r3, addr);
                kbh[np * 2 + 0][0] = r0; kbh[np * 2 + 0][1] = r1;
                kbh[np * 2 + 1][0] = r2; kbh[np * 2 + 1][1] = r3;
                LDSM_X4(r0, r1, r2, r3, addr + (KLO_B - KHI_B));
                kbl[np * 2 + 0][0] = r0; kbl[np * 2 + 0][1] = r1;
                kbl[np * 2 + 1][0] = r2; kbl[np * 2 + 1][1] = r3;
            }
#pragma unroll
            for (int j = 0; j < 8; j++) {
                MMA_BF16(S_[j], qh_[kk], kbh[j]);
                MMA_BF16(S_[j], qh_[kk], kbl[j]);
                MMA_BF16(S_[j], ql_[kk], kbh[j]);
            }
        }

        // ---- online softmax (2 rows per thread: g and g+8) ----
        float mt0 = -1e30f, mt1 = -1e30f;
#pragma unroll
        for (int j = 0; j < 8; j++) {
            mt0 = fmaxf(mt0, fmaxf(S_[j][0], S_[j][1]));
            mt1 = fmaxf(mt1, fmaxf(S_[j][2], S_[j][3]));
        }
        mt0 = fmaxf(mt0, __shfl_xor_sync(0xffffffffu, mt0, 1));
        mt0 = fmaxf(mt0, __shfl_xor_sync(0xffffffffu, mt0, 2));
        mt1 = fmaxf(mt1, __shfl_xor_sync(0xffffffffu, mt1, 1));
        mt1 = fmaxf(mt1, __shfl_xor_sync(0xffffffffu, mt1, 2));

        const float mn0 = fmaxf(m0, mt0);
        const float mn1 = fmaxf(m1, mt1);
        const float al0 = fexp(m0 - mn0);
        const float al1 = fexp(m1 - mn1);

        float s0 = 0.0f, s1 = 0.0f;
#pragma unroll
        for (int j = 0; j < 8; j++) {
            S_[j][0] = fexp(S_[j][0] - mn0);
            S_[j][1] = fexp(S_[j][1] - mn0);
            S_[j][2] = fexp(S_[j][2] - mn1);
            S_[j][3] = fexp(S_[j][3] - mn1);
            s0 += S_[j][0] + S_[j][1];
            s1 += S_[j][2] + S_[j][3];
        }
        s0 += __shfl_xor_sync(0xffffffffu, s0, 1);
        s0 += __shfl_xor_sync(0xffffffffu, s0, 2);
        s1 += __shfl_xor_sync(0xffffffffu, s1, 1);
        s1 += __shfl_xor_sync(0xffffffffu, s1, 2);

        l0 = l0 * al0 + s0;
        l1 = l1 * al1 + s1;
        m0 = mn0;
        m1 = mn1;

#pragma unroll
        for (int j = 0; j < 8; j++) {
            O_[j][0] *= al0;
            O_[j][1] *= al0;
            O_[j][2] *= al1;
            O_[j][3] *= al1;
        }

        // ---- O += P V (3-term split; P from registers) ----
#pragma unroll
        for (int kk = 0; kk < 4; kk++) {
            const int t0 = 2 * kk, t1 = 2 * kk + 1;
            uint32_t ah[4], al_[4];
            ah[0] = packbf(S_[t0][1], S_[t0][0]);
            ah[1] = packbf(S_[t0][3], S_[t0][2]);
            ah[2] = packbf(S_[t1][1], S_[t1][0]);
            ah[3] = packbf(S_[t1][3], S_[t1][2]);
            al_[0] = packbf(S_[t0][1] - bf_hi(ah[0]), S_[t0][0] - bf_lo(ah[0]));
            al_[1] = packbf(S_[t0][3] - bf_hi(ah[1]), S_[t0][2] - bf_lo(ah[1]));
            al_[2] = packbf(S_[t1][1] - bf_hi(ah[2]), S_[t1][0] - bf_lo(ah[2]));
            al_[3] = packbf(S_[t1][3] - bf_hi(ah[3]), S_[t1][2] - bf_lo(ah[3]));

            uint32_t vbh[8][2], vbl[8][2];
#pragma unroll
            for (int np = 0; np < 4; np++) {
                uint32_t r0, r1, r2, r3;
                uint32_t addr = smb + VHI_B + (np * 16 + bRow) * KVP_B +
                                (bK + kk * 16) * 2;
                LDSM_X4(r0, r1, r2, r3, addr);
                vbh[np * 2 + 0][0] = r0; vbh[np * 2 + 0][1] = r1;
                vbh[np * 2 + 1][0] = r2; vbh[np * 2 + 1][1] = r3;
                LDSM_X4(r0, r1, r2, r3, addr + (VLO_B - VHI_B));
                vbl[np * 2 + 0][0] = r0; vbl[np * 2 + 0][1] = r1;
                vbl[np * 2 + 1][0] = r2; vbl[np * 2 + 1][1] = r3;
            }
#pragma unroll
            for (int j = 0; j < 8; j++) {
                MMA_BF16(O_[j], ah, vbh[j]);
                MMA_BF16(O_[j], ah, vbl[j]);
                MMA_BF16(O_[j], al_, vbh[j]);
            }
        }
        __syncthreads();
    }

    // ---- epilogue: normalize, write to [B,S,D] ----
    const float il0 = 1.0f / l0;
    const float il1 = 1.0f / l1;
    const int g = lid >> 2;
    const int t4 = lid & 3;
    const size_t row0 = (size_t)b * SEQ + q0 + warpQ + g;
#pragma unroll
    for (int j = 0; j < 8; j++) {
        const int col = h * 64 + j * 8 + t4 * 2;
        float2 v0, v1;
        v0.x = O_[j][0] * il0;
        v0.y = O_[j][1] * il0;
        v1.x = O_[j][2] * il1;
        v1.y = O_[j][3] * il1;
        *(float2*)(o + row0 * D_MODEL + col) = v0;
        *(float2*)(o + (row0 + 8) * D_MODEL + col) = v1;
    }
}

// ---------------------------------------------------------------------------
// Launch
// ---------------------------------------------------------------------------
static void run_tensor_gemm(const float* A, const float* W, const float* bias,
                            float* C,
                            __nv_bfloat16* ahi, __nv_bfloat16* alo,
                            __nv_bfloat16* bhi, __nv_bfloat16* blo) {
    split_kernel<<<(M_ROWS * D_MODEL / 4 + 255) / 256, 256>>>(A, ahi, alo,
                                                              M_ROWS * D_MODEL / 4);
    splitT_kernel<<<dim3(32, 32), dim3(32, 32)>>>(W, bhi, blo);
    dim3 grid(D_MODEL / 128, M_ROWS / 128);
    hgemm_kernel<<<grid, 256, HG_SMEM>>>(ahi, alo, bhi, blo, bias, C,
                                         M_ROWS, D_MODEL, D_MODEL);
}

extern "C" void kernel_launch(void* const* d_in, const int* in_sizes, int n_in,
                              void* d_out, int out_size) {
    const float* Q  = (const float*)d_in[0];
    const float* K  = (const float*)d_in[1];
    const float* V  = (const float*)d_in[2];
    const float* Wq = (const float*)d_in[3];
    const float* bq = (const float*)d_in[4];
    const float* Wk = (const float*)d_in[5];
    const float* bk = (const float*)d_in[6];
    const float* Wv = (const float*)d_in[7];
    const float* bv = (const float*)d_in[8];
    const float* Wo = (const float*)d_in[9];
    const float* bo = (const float*)d_in[10];
    float* out = (float*)d_out;

    float* dq;    cudaGetSymbolAddress((void**)&dq,    g_q);
    float* dk;    cudaGetSymbolAddress((void**)&dk,    g_k);
    float* dv;    cudaGetSymbolAddress((void**)&dv,    g_v);
    float* dattn; cudaGetSymbolAddress((void**)&dattn, g_attn);
    __nv_bfloat16* ahi; cudaGetSymbolAddress((void**)&ahi, g_ahi);
    __nv_bfloat16* alo; cudaGetSymbolAddress((void**)&alo, g_alo);
    __nv_bfloat16* bhi; cudaGetSymbolAddress((void**)&bhi, g_bhi);
    __nv_bfloat16* blo; cudaGetSymbolAddress((void**)&blo, g_blo);
    __nv_bfloat16* qhi; cudaGetSymbolAddress((void**)&qhi, g_qhi);
    __nv_bfloat16* qlo; cudaGetSymbolAddress((void**)&qlo, g_qlo);
    __nv_bfloat16* khi; cudaGetSymbolAddress((void**)&khi, g_khi);
    __nv_bfloat16* klo; cudaGetSymbolAddress((void**)&klo, g_klo);
    __nv_bfloat16* vthi; cudaGetSymbolAddress((void**)&vthi, g_vthi);
    __nv_bfloat16* vtlo; cudaGetSymbolAddress((void**)&vtlo, g_vtlo);

    cudaFuncSetAttribute(hgemm_kernel,
                         cudaFuncAttributeMaxDynamicSharedMemorySize, HG_SMEM);
    cudaFuncSetAttribute(flash_hmma_kernel,
                         cudaFuncAttributeMaxDynamicSharedMemorySize, FA_SMEM);

    // projections
    run_tensor_gemm(Q, Wq, bq, dq, ahi, alo, bhi, blo);
    run_tensor_gemm(K, Wk, bk, dk, ahi, alo, bhi, blo);
    run_tensor_gemm(V, Wv, bv, dv, ahi, alo, bhi, blo);

    // attention pre-split (head-major; Q prescaled by 1/sqrt(Dh))
    const int nthreads = M_ROWS * D_MODEL / 4;
    split_head_kernel<<<(nthreads + 255) / 256, 256>>>(dq, qhi, qlo, 0.125f);
    split_head_kernel<<<(nthreads + 255) / 256, 256>>>(dk, khi, klo, 1.0f);
    split_vt_kernel<<<dim3(SEQ / 64, BATCH * NUM_HEADS), 256>>>(dv, vthi, vtlo);

    // attention
    flash_hmma_kernel<<<dim3(SEQ / 128, BATCH * NUM_HEADS), 256, FA_SMEM>>>(
        qhi, qlo, khi, klo, vthi, vtlo, dattn);

    // output projection
    run_tensor_gemm(dattn, Wo, bo, out, ahi, alo, bhi, blo);
}

// round 7
// speedup vs baseline: 4.2742x; 1.1099x over previous
#include <cuda_runtime.h>
#include <cuda_bf16.h>
#include <math.h>
#include <stdint.h>

// ---------------------------------------------------------------------------
// Problem constants
// ---------------------------------------------------------------------------
#define D_MODEL   1024
#define NUM_HEADS 16
#define HEAD_DIM  64
#define BATCH     2
#define SEQ       2048
#define M_ROWS    (BATCH * SEQ)      // 4096

// ---------------------------------------------------------------------------
// Scratch (static device globals; no cudaMalloc allowed)
// ---------------------------------------------------------------------------
__device__ __nv_bfloat16 g_ahi[M_ROWS * D_MODEL];    // A operand hi (row-major)
__device__ __nv_bfloat16 g_alo[M_ROWS * D_MODEL];
__device__ __nv_bfloat16 g_bhi[D_MODEL * D_MODEL];   // W^T [N,K] K-major
__device__ __nv_bfloat16 g_blo[D_MODEL * D_MODEL];

__device__ __nv_bfloat16 g_qhi[M_ROWS * D_MODEL];    // [B,H,S,64], prescaled
__device__ __nv_bfloat16 g_qlo[M_ROWS * D_MODEL];
__device__ __nv_bfloat16 g_khi[M_ROWS * D_MODEL];    // [B,H,S,64]
__device__ __nv_bfloat16 g_klo[M_ROWS * D_MODEL];
__device__ __nv_bfloat16 g_vthi[M_ROWS * D_MODEL];   // [B,H,64,S]
__device__ __nv_bfloat16 g_vtlo[M_ROWS * D_MODEL];

// ---------------------------------------------------------------------------
// Helpers
// ---------------------------------------------------------------------------
__device__ __forceinline__ uint32_t smem_u32(const void* p) {
    uint32_t a;
    asm("{ .reg .u64 t; cvta.to.shared.u64 t, %1; cvt.u32.u64 %0, t; }"
        : "=r"(a) : "l"(p));
    return a;
}

#define LDSM_X4(r0, r1, r2, r3, addr) \
    asm volatile("ldmatrix.sync.aligned.m8n8.x4.shared.b16 {%0,%1,%2,%3}, [%4];" \
                 : "=r"(r0), "=r"(r1), "=r"(r2), "=r"(r3) : "r"(addr))

#define MMA_BF16(c, a, b) \
    asm volatile("mma.sync.aligned.m16n8k16.row.col.f32.bf16.bf16.f32 " \
                 "{%0,%1,%2,%3}, {%4,%5,%6,%7}, {%8,%9}, {%0,%1,%2,%3};" \
                 : "+f"((c)[0]), "+f"((c)[1]), "+f"((c)[2]), "+f"((c)[3]) \
                 : "r"((a)[0]), "r"((a)[1]), "r"((a)[2]), "r"((a)[3]), \
                   "r"((b)[0]), "r"((b)[1]))

#define CP_ASYNC16(dst, src) \
    asm volatile("cp.async.cg.shared.global [%0], [%1], 16;" \
                 :: "r"(dst), "l"(src) : "memory")
#define CP_COMMIT() asm volatile("cp.async.commit_group;" ::: "memory")
#define CP_WAIT(n)  asm volatile("cp.async.wait_group %0;" :: "n"(n) : "memory")

__device__ __forceinline__ uint32_t packbf(float hi, float lo) {
    uint32_t r;
    asm("cvt.rn.bf16x2.f32 %0, %1, %2;" : "=r"(r) : "f"(hi), "f"(lo));
    return r;
}
__device__ __forceinline__ float bf_lo(uint32_t h) { return __int_as_float(h << 16); }
__device__ __forceinline__ float bf_hi(uint32_t h) { return __int_as_float(h & 0xffff0000u); }

// Fast e^x (x<=0, clamped); deg-6 2^f poly + exponent bit-trick. No MUFU.
__device__ __forceinline__ float fexp(float x) {
    x = fmaxf(x, -80.0f);
    float t = x * 1.4426950408889634f;
    float n = floorf(t);
    float f = t - n;
    float p = 1.5403530393e-4f;
    p = fmaf(p, f, 1.3333558146e-3f);
    p = fmaf(p, f, 9.6181291076e-3f);
    p = fmaf(p, f, 5.5504108665e-2f);
    p = fmaf(p, f, 2.4022650696e-1f);
    p = fmaf(p, f, 6.9314718056e-1f);
    p = fmaf(p, f, 1.0f);
    return __int_as_float(__float_as_int(p) + (((int)n) << 23));
}

// split a pair of floats into bf16 hi/lo packed words
__device__ __forceinline__ void split2(float a, float b,
                                       __nv_bfloat162* hp, __nv_bfloat162* lp) {
    __nv_bfloat16 h0 = __float2bfloat16(a);
    __nv_bfloat16 h1 = __float2bfloat16(b);
    *hp = __halves2bfloat162(h0, h1);
    *lp = __halves2bfloat162(__float2bfloat16(a - __bfloat162float(h0)),
                             __float2bfloat16(b - __bfloat162float(h1)));
}

// ---------------------------------------------------------------------------
// fp32 -> bf16 hi/lo split (row-major, for GEMM A operands)
// ---------------------------------------------------------------------------
__global__ __launch_bounds__(256)
void split_kernel(const float* __restrict__ in,
                  __nv_bfloat16* __restrict__ hi,
                  __nv_bfloat16* __restrict__ lo, int n4) {
    int i = blockIdx.x * blockDim.x + threadIdx.x;
    if (i >= n4) return;
    float4 v = ((const float4*)in)[i];
    float a[4] = {v.x, v.y, v.z, v.w};
    __nv_bfloat16 h[4], l[4];
#pragma unroll
    for (int j = 0; j < 4; j++) {
        h[j] = __float2bfloat16(a[j]);
        l[j] = __float2bfloat16(a[j] - __bfloat162float(h[j]));
    }
    __nv_bfloat162* h2 = (__nv_bfloat162*)hi;
    __nv_bfloat162* l2 = (__nv_bfloat162*)lo;
    h2[2 * i + 0] = __halves2bfloat162(h[0], h[1]);
    h2[2 * i + 1] = __halves2bfloat162(h[2], h[3]);
    l2[2 * i + 0] = __halves2bfloat162(l[0], l[1]);
    l2[2 * i + 1] = __halves2bfloat162(l[2], l[3]);
}

// ---------------------------------------------------------------------------
// W[K,N] fp32 -> transposed bf16 hi/lo  (Bt[N,K], K-major)
// ---------------------------------------------------------------------------
__global__ __launch_bounds__(1024)
void splitT_kernel(const float* __restrict__ W,
                   __nv_bfloat16* __restrict__ th,
                   __nv_bfloat16* __restrict__ tl) {
    __shared__ float tile[32][33];
    int k = blockIdx.y * 32 + threadIdx.y;
    int n = blockIdx.x * 32 + threadIdx.x;
    tile[threadIdx.y][threadIdx.x] = W[(size_t)k * D_MODEL + n];
    __syncthreads();
    int on = blockIdx.x * 32 + threadIdx.y;
    int ok = blockIdx.y * 32 + threadIdx.x;
    float v = tile[threadIdx.x][threadIdx.y];
    __nv_bfloat16 h = __float2bfloat16(v);
    th[(size_t)on * D_MODEL + ok] = h;
    tl[(size_t)on * D_MODEL + ok] = __float2bfloat16(v - __bfloat162float(h));
}

// ---------------------------------------------------------------------------
// HMMA bf16 split GEMM with cp.async 2-stage pipeline and fused epilogues.
//   mode 0: Cf32[M,N] = .. + bias                       (final projection)
//   mode 1: bf16 hi/lo head-major [B,H,S,64], *scale    (Q/K projections)
//   mode 2: bf16 hi/lo transposed [B,H,64,S]            (V projection)
// ---------------------------------------------------------------------------
#define BKG        32
#define ROWPAD     40
#define OP_BYTES   (128 * ROWPAD * 2)
#define STAGE_B    (4 * OP_BYTES)
#define HG_SMEM    (2 * STAGE_B)

__global__ __launch_bounds__(256)
void hgemm_kernel(const __nv_bfloat16* __restrict__ Ahi,
                  const __nv_bfloat16* __restrict__ Alo,
                  const __nv_bfloat16* __restrict__ Bhi,
                  const __nv_bfloat16* __restrict__ Blo,
                  const float* __restrict__ bias,
                  float* __restrict__ C,
                  __nv_bfloat16* __restrict__ Hh,
                  __nv_bfloat16* __restrict__ Hl,
                  int M, int N, int K, int mode, float scale) {
    extern __shared__ char smem[];
    const uint32_t smem_base = smem_u32(smem);

    const int tid = threadIdx.x;
    const int wid = tid >> 5;
    const int lid = tid & 31;
    const int rowBase = blockIdx.y * 128;
    const int colBase = blockIdx.x * 128;
    const int warpM = (wid >> 2) * 64;
    const int warpN = (wid & 3) * 32;

    const __nv_bfloat16* gsrc0 = Ahi + (size_t)rowBase * K;
    const __nv_bfloat16* gsrc1 = Alo + (size_t)rowBase * K;
    const __nv_bfloat16* gsrc2 = Bhi + (size_t)colBase * K;
    const __nv_bfloat16* gsrc3 = Blo + (size_t)colBase * K;

    const int ldRow0 = tid >> 2;
    const int ldCol  = (tid & 3) * 8;

    const int aLaneRow = lid & 15;
    const int aLaneK   = (lid >> 4) * 8;
    const int bLaneRow = (lid & 7) + ((lid >> 4) << 3);
    const int bLaneK   = ((lid >> 3) & 1) * 8;

    float acc[4][4][4];
#pragma unroll
    for (int i = 0; i < 4; i++)
#pragma unroll
        for (int j = 0; j < 4; j++)
#pragma unroll
            for (int c = 0; c < 4; c++) acc[i][j][c] = 0.0f;

    const int NIT = K / BKG;   // 32

    auto issue_stage = [&](int it) {
        const int k0 = it * BKG;
        const uint32_t stg = smem_base + (it & 1) * STAGE_B;
#pragma unroll
        for (int op = 0; op < 4; op++) {
            const __nv_bfloat16* src =
                (op == 0) ? gsrc0 : (op == 1) ? gsrc1 : (op == 2) ? gsrc2 : gsrc3;
#pragma unroll
            for (int h = 0; h < 2; h++) {
                int r = ldRow0 + h * 64;
                CP_ASYNC16(stg + op * OP_BYTES + r * (ROWPAD * 2) + ldCol * 2,
                           src + (size_t)r * K + k0 + ldCol);
            }
        }
        CP_COMMIT();
    };

    issue_stage(0);

    for (int it = 0; it < NIT; it++) {
        const int s = it & 1;
        const uint32_t stage = smem_base + s * STAGE_B;

        if (it + 1 < NIT) {
            issue_stage(it + 1);
            CP_WAIT(1);
        } else {
            CP_WAIT(0);
        }
        __syncthreads();

        const uint32_t aHiBase = stage + 0 * OP_BYTES +
                                 (warpM + aLaneRow) * (ROWPAD * 2) + aLaneK * 2;
        const uint32_t aLoBase = aHiBase + OP_BYTES;
        const uint32_t bHiBase = stage + 2 * OP_BYTES +
                                 (warpN + bLaneRow) * (ROWPAD * 2) + bLaneK * 2;
        const uint32_t bLoBase = bHiBase + OP_BYTES;

#pragma unroll
        for (int ks = 0; ks < 2; ks++) {
            const uint32_t koff = ks * 32;

            uint32_t ah[4][4], al[4][4];
#pragma unroll
            for (int mb = 0; mb < 4; mb++) {
                LDSM_X4(ah[mb][0], ah[mb][1], ah[mb][2], ah[mb][3],
                        aHiBase + mb * 16 * (ROWPAD * 2) + koff);
                LDSM_X4(al[mb][0], al[mb][1], al[mb][2], al[mb][3],
                        aLoBase + mb * 16 * (ROWPAD * 2) + koff);
            }
            uint32_t bh[4][2], bl[4][2];
#pragma unroll
            for (int np = 0; np < 2; np++) {
                uint32_t r0, r1, r2, r3;
                LDSM_X4(r0, r1, r2, r3, bHiBase + np * 16 * (ROWPAD * 2) + koff);
                bh[np * 2 + 0][0] = r0; bh[np * 2 + 0][1] = r1;
                bh[np * 2 + 1][0] = r2; bh[np * 2 + 1][1] = r3;
                LDSM_X4(r0, r1, r2, r3, bLoBase + np * 16 * (ROWPAD * 2) + koff);
                bl[np * 2 + 0][0] = r0; bl[np * 2 + 0][1] = r1;
                bl[np * 2 + 1][0] = r2; bl[np * 2 + 1][1] = r3;
            }

#pragma unroll
            for (int mb = 0; mb < 4; mb++)
#pragma unroll
                for (int nb = 0; nb < 4; nb++) {
                    MMA_BF16(acc[mb][nb], ah[mb], bh[nb]);
                    MMA_BF16(acc[mb][nb], ah[mb], bl[nb]);
                    MMA_BF16(acc[mb][nb], al[mb], bh[nb]);
                }
        }
        __syncthreads();   // all warps done with stage s before it's refilled
    }

    // ---- fused epilogue ----
    const int gid = lid >> 2;
    const int tig = lid & 3;
#pragma unroll
    for (int mb = 0; mb < 4; mb++) {
        const int r0 = rowBase + warpM + mb * 16 + gid;
        const int r1 = r0 + 8;
#pragma unroll
        for (int nb = 0; nb < 4; nb++) {
            const int col = colBase + warpN + nb * 8 + tig * 2;
            const float2 bv = *(const float2*)(bias + col);
            float v00 = acc[mb][nb][0] + bv.x;
            float v01 = acc[mb][nb][1] + bv.y;
            float v10 = acc[mb][nb][2] + bv.x;
            float v11 = acc[mb][nb][3] + bv.y;

            if (mode == 0) {
                *(float2*)(C + (size_t)r0 * N + col) = make_float2(v00, v01);
                *(float2*)(C + (size_t)r1 * N + col) = make_float2(v10, v11);
            } else if (mode == 1) {
                v00 *= scale; v01 *= scale; v10 *= scale; v11 *= scale;
                const int h_ = col >> 6, d_ = col & 63;
                const int b_ = r0 >> 11;
                const int s0 = r0 & (SEQ - 1), s1 = r1 & (SEQ - 1);
                const size_t o0 = (((size_t)(b_ * NUM_HEADS + h_)) * SEQ + s0) * 64 + d_;
                const size_t o1 = (((size_t)(b_ * NUM_HEADS + h_)) * SEQ + s1) * 64 + d_;
                split2(v00, v01, (__nv_bfloat162*)(Hh + o0), (__nv_bfloat162*)(Hl + o0));
                split2(v10, v11, (__nv_bfloat162*)(Hh + o1), (__nv_bfloat162*)(Hl + o1));
            } else {
                const int h_ = col >> 6, d_ = col & 63;
                const int b_ = r0 >> 11;
                const int s0 = r0 & (SEQ - 1), s1 = r1 & (SEQ - 1);
                const size_t db = (size_t)(b_ * NUM_HEADS + h_) * 64 + d_;
                float vv[4] = {v00, v01, v10, v11};
                const size_t offs[4] = {db * SEQ + s0, (db + 1) * SEQ + s0,
                                        db * SEQ + s1, (db + 1) * SEQ + s1};
#pragma unroll
                for (int e = 0; e < 4; e++) {
                    __nv_bfloat16 hh = __float2bfloat16(vv[e]);
                    Hh[offs[e]] = hh;
                    Hl[offs[e]] = __float2bfloat16(vv[e] - __bfloat162float(hh));
                }
            }
        }
    }
}

// ---------------------------------------------------------------------------
// HMMA flash attention (compute identical to round 6; epilogue now writes
// bf16 hi/lo row-major [B*S, D] — the A operand of the output projection).
// ---------------------------------------------------------------------------
#define KVP_B   144
#define QHI_B   0
#define QLO_B   18432
#define KHI_B   36864
#define KLO_B   46080
#define VHI_B   55296
#define VLO_B   64512
#define FA_SMEM 73728

__global__ __launch_bounds__(256, 1)
void flash_hmma_kernel(const __nv_bfloat16* __restrict__ qhi,
                       const __nv_bfloat16* __restrict__ qlo,
                       const __nv_bfloat16* __restrict__ khi,
                       const __nv_bfloat16* __restrict__ klo,
                       const __nv_bfloat16* __restrict__ vthi,
                       const __nv_bfloat16* __restrict__ vtlo,
                       __nv_bfloat16* __restrict__ ohi,
                       __nv_bfloat16* __restrict__ olo) {
    extern __shared__ char smc[];
    const uint32_t smb = smem_u32(smc);

    const int tid = threadIdx.x;
    const int wid = tid >> 5;
    const int lid = tid & 31;
    const int bh = blockIdx.y;
    const int b = bh >> 4, h = bh & 15;
    const int q0 = blockIdx.x * 128;

    const size_t qbase = ((size_t)bh * SEQ + q0) * 64;
    const size_t kbase = (size_t)bh * SEQ * 64;
    const size_t vbase = (size_t)bh * 64 * SEQ;

#pragma unroll
    for (int i = 0; i < 4; i++) {
        int e = tid + i * 256;
        int r = e >> 3, c = e & 7;
        *(uint4*)(smc + QHI_B + r * KVP_B + c * 16) =
            *(const uint4*)(qhi + qbase + (size_t)r * 64 + c * 8);
        *(uint4*)(smc + QLO_B + r * KVP_B + c * 16) =
            *(const uint4*)(qlo + qbase + (size_t)r * 64 + c * 8);
    }
    __syncthreads();

    const int warpQ = wid * 16;
    const int aRow = lid & 15;
    const int aK   = (lid >> 4) * 8;
    uint32_t qh_[4][4], ql_[4][4];
#pragma unroll
    for (int kk = 0; kk < 4; kk++) {
        uint32_t addr = smb + QHI_B + (warpQ + aRow) * KVP_B + (aK + kk * 16) * 2;
        LDSM_X4(qh_[kk][0], qh_[kk][1], qh_[kk][2], qh_[kk][3], addr);
        LDSM_X4(ql_[kk][0], ql_[kk][1], ql_[kk][2], ql_[kk][3],
                addr + (QLO_B - QHI_B));
    }

    float O_[8][4];
#pragma unroll
    for (int j = 0; j < 8; j++)
#pragma unroll
        for (int c = 0; c < 4; c++) O_[j][c] = 0.0f;
    float m0 = -1e30f, m1 = -1e30f, l0 = 0.0f, l1 = 0.0f;

    const int bRow = (lid & 7) + ((lid >> 4) << 3);
    const int bK   = ((lid >> 3) & 1) * 8;

    for (int kt = 0; kt < SEQ / 64; kt++) {
        const int k0 = kt * 64;

#pragma unroll
        for (int i = 0; i < 2; i++) {
            int e = tid + i * 256;
            int r = e >> 3, c = e & 7;
            *(uint4*)(smc + KHI_B + r * KVP_B + c * 16) =
                *(const uint4*)(khi + kbase + (size_t)(k0 + r) * 64 + c * 8);
            *(uint4*)(smc + KLO_B + r * KVP_B + c * 16) =
                *(const uint4*)(klo + kbase + (size_t)(k0 + r) * 64 + c * 8);
            *(uint4*)(smc + VHI_B + r * KVP_B + c * 16) =
                *(const uint4*)(vthi + vbase + (size_t)r * SEQ + k0 + c * 8);
            *(uint4*)(smc + VLO_B + r * KVP_B + c * 16) =
                *(const uint4*)(vtlo + vbase + (size_t)r * SEQ + k0 + c * 8);
        }
        __syncthreads();

        float S_[8][4];
#pragma unroll
        for (int j = 0; j < 8; j++)
#pragma unroll
            for (int c = 0; c < 4; c++) S_[j][c] = 0.0f;

#pragma unroll
        for (int kk = 0; kk < 4; kk++) {
            uint32_t kbh[8][2], kbl[8][2];
#pragma unroll
            for (int np = 0; np < 4; np++) {
                uint32_t r0, r1, r2, r3;
                uint32_t addr = smb + KHI_B + (np * 16 + bRow) * KVP_B +
                                (bK + kk * 16) * 2;
                LDSM_X4(r0, r1, r2, r3, addr);
                kbh[np * 2 + 0][0] = r0; kbh[np * 2 + 0][1] = r1;
                kbh[np * 2 + 1][0] = r2; kbh[np * 2 + 1][1] = r3;
                LDSM_X4(r0, r1, r2, r3, addr + (KLO_B - KHI_B));
                kbl[np * 2 + 0][0] = r0; kbl[np * 2 + 0][1] = r1;
                kbl[np * 2 + 1][0] = r2; kbl[np * 2 + 1][1] = r3;
            }
#pragma unroll
            for (int j = 0; j < 8; j++) {
                MMA_BF16(S_[j], qh_[kk], kbh[j]);
                MMA_BF16(S_[j], qh_[kk], kbl[j]);
                MMA_BF16(S_[j], ql_[kk], kbh[j]);
            }
        }

        float mt0 = -1e30f, mt1 = -1e30f;
#pragma unroll
        for (int j = 0; j < 8; j++) {
            mt0 = fmaxf(mt0, fmaxf(S_[j][0], S_[j][1]));
            mt1 = fmaxf(mt1, fmaxf(S_[j][2], S_[j][3]));
        }
        mt0 = fmaxf(mt0, __shfl_xor_sync(0xffffffffu, mt0, 1));
        mt0 = fmaxf(mt0, __shfl_xor_sync(0xffffffffu, mt0, 2));
        mt1 = fmaxf(mt1, __shfl_xor_sync(0xffffffffu, mt1, 1));
        mt1 = fmaxf(mt1, __shfl_xor_sync(0xffffffffu, mt1, 2));

        const float mn0 = fmaxf(m0, mt0);
        const float mn1 = fmaxf(m1, mt1);
        const float al0 = fexp(m0 - mn0);
        const float al1 = fexp(m1 - mn1);

        float s0 = 0.0f, s1 = 0.0f;
#pragma unroll
        for (int j = 0; j < 8; j++) {
            S_[j][0] = fexp(S_[j][0] - mn0);
            S_[j][1] = fexp(S_[j][1] - mn0);
            S_[j][2] = fexp(S_[j][2] - mn1);
            S_[j][3] = fexp(S_[j][3] - mn1);
            s0 += S_[j][0] + S_[j][1];
            s1 += S_[j][2] + S_[j][3];
        }
        s0 += __shfl_xor_sync(0xffffffffu, s0, 1);
        s0 += __shfl_xor_sync(0xffffffffu, s0, 2);
        s1 += __shfl_xor_sync(0xffffffffu, s1, 1);
        s1 += __shfl_xor_sync(0xffffffffu, s1, 2);

        l0 = l0 * al0 + s0;
        l1 = l1 * al1 + s1;
        m0 = mn0;
        m1 = mn1;

#pragma unroll
        for (int j = 0; j < 8; j++) {
            O_[j][0] *= al0;
            O_[j][1] *= al0;
            O_[j][2] *= al1;
            O_[j][3] *= al1;
        }

#pragma unroll
        for (int kk = 0; kk < 4; kk++) {
            const int t0 = 2 * kk, t1 = 2 * kk + 1;
            uint32_t ah[4], al_[4];
            ah[0] = packbf(S_[t0][1], S_[t0][0]);
            ah[1] = packbf(S_[t0][3], S_[t0][2]);
            ah[2] = packbf(S_[t1][1], S_[t1][0]);
            ah[3] = packbf(S_[t1][3], S_[t1][2]);
            al_[0] = packbf(S_[t0][1] - bf_hi(ah[0]), S_[t0][0] - bf_lo(ah[0]));
            al_[1] = packbf(S_[t0][3] - bf_hi(ah[1]), S_[t0][2] - bf_lo(ah[1]));
            al_[2] = packbf(S_[t1][1] - bf_hi(ah[2]), S_[t1][0] - bf_lo(ah[2]));
            al_[3] = packbf(S_[t1][3] - bf_hi(ah[3]), S_[t1][2] - bf_lo(ah[3]));

            uint32_t vbh[8][2], vbl[8][2];
#pragma unroll
            for (int np = 0; np < 4; np++) {
                uint32_t r0, r1, r2, r3;
                uint32_t addr = smb + VHI_B + (np * 16 + bRow) * KVP_B +
                                (bK + kk * 16) * 2;
                LDSM_X4(r0, r1, r2, r3, addr);
                vbh[np * 2 + 0][0] = r0; vbh[np * 2 + 0][1] = r1;
                vbh[np * 2 + 1][0] = r2; vbh[np * 2 + 1][1] = r3;
                LDSM_X4(r0, r1, r2, r3, addr + (VLO_B - VHI_B));
                vbl[np * 2 + 0][0] = r0; vbl[np * 2 + 0][1] = r1;
                vbl[np * 2 + 1][0] = r2; vbl[np * 2 + 1][1] = r3;
            }
#pragma unroll
            for (int j = 0; j < 8; j++) {
                MMA_BF16(O_[j], ah, vbh[j]);
                MMA_BF16(O_[j], ah, vbl[j]);
                MMA_BF16(O_[j], al_, vbh[j]);
            }
        }
        __syncthreads();
    }

    // ---- epilogue: normalize, split, write bf16 hi/lo [B*S, D] ----
    const float il0 = 1.0f / l0;
    const float il1 = 1.0f / l1;
    const int g = lid >> 2;
    const int t4 = lid & 3;
    const size_t row0 = (size_t)b * SEQ + q0 + warpQ + g;
#pragma unroll
    for (int j = 0; j < 8; j++) {
        const int col = h * 64 + j * 8 + t4 * 2;
        const size_t o0 = row0 * D_MODEL + col;
        const size_t o1 = (row0 + 8) * D_MODEL + col;
        split2(O_[j][0] * il0, O_[j][1] * il0,
               (__nv_bfloat162*)(ohi + o0), (__nv_bfloat162*)(olo + o0));
        split2(O_[j][2] * il1, O_[j][3] * il1,
               (__nv_bfloat162*)(ohi + o1), (__nv_bfloat162*)(olo + o1));
    }
}

// ---------------------------------------------------------------------------
// Launch
// ---------------------------------------------------------------------------
extern "C" void kernel_launch(void* const* d_in, const int* in_sizes, int n_in,
                              void* d_out, int out_size) {
    const float* Q  = (const float*)d_in[0];
    const float* K  = (const float*)d_in[1];
    const float* V  = (const float*)d_in[2];
    const float* Wq = (const float*)d_in[3];
    const float* bq = (const float*)d_in[4];
    const float* Wk = (const float*)d_in[5];
    const float* bk = (const float*)d_in[6];
    const float* Wv = (const float*)d_in[7];
    const float* bv = (const float*)d_in[8];
    const float* Wo = (const float*)d_in[9];
    const float* bo = (const float*)d_in[10];
    float* out = (float*)d_out;

    __nv_bfloat16 *ahi, *alo, *bhi, *blo, *qhi, *qlo, *khi, *klo, *vthi, *vtlo;
    cudaGetSymbolAddress((void**)&ahi, g_ahi);
    cudaGetSymbolAddress((void**)&alo, g_alo);
    cudaGetSymbolAddress((void**)&bhi, g_bhi);
    cudaGetSymbolAddress((void**)&blo, g_blo);
    cudaGetSymbolAddress((void**)&qhi, g_qhi);
    cudaGetSymbolAddress((void**)&qlo, g_qlo);
    cudaGetSymbolAddress((void**)&khi, g_khi);
    cudaGetSymbolAddress((void**)&klo, g_klo);
    cudaGetSymbolAddress((void**)&vthi, g_vthi);
    cudaGetSymbolAddress((void**)&vtlo, g_vtlo);

    cudaFuncSetAttribute(hgemm_kernel,
                         cudaFuncAttributeMaxDynamicSharedMemorySize, HG_SMEM);
    cudaFuncSetAttribute(flash_hmma_kernel,
                         cudaFuncAttributeMaxDynamicSharedMemorySize, FA_SMEM);

    const int nsplit = (M_ROWS * D_MODEL / 4 + 255) / 256;
    dim3 ggrid(D_MODEL / 128, M_ROWS / 128);

    // Q projection -> qhi/qlo (head-major, prescaled)
    split_kernel<<<nsplit, 256>>>(Q, ahi, alo, M_ROWS * D_MODEL / 4);
    splitT_kernel<<<dim3(32, 32), dim3(32, 32)>>>(Wq, bhi, blo);
    hgemm_kernel<<<ggrid, 256, HG_SMEM>>>(ahi, alo, bhi, blo, bq, nullptr,
                                          qhi, qlo, M_ROWS, D_MODEL, D_MODEL,
                                          1, 0.125f);

    // K projection -> khi/klo (head-major)
    split_kernel<<<nsplit, 256>>>(K, ahi, alo, M_ROWS * D_MODEL / 4);
    splitT_kernel<<<dim3(32, 32), dim3(32, 32)>>>(Wk, bhi, blo);
    hgemm_kernel<<<ggrid, 256, HG_SMEM>>>(ahi, alo, bhi, blo, bk, nullptr,
                                          khi, klo, M_ROWS, D_MODEL, D_MODEL,
                                          1, 1.0f);

    // V projection -> vthi/vtlo (transposed head-major)
    split_kernel<<<nsplit, 256>>>(V, ahi, alo, M_ROWS * D_MODEL / 4);
    splitT_kernel<<<dim3(32, 32), dim3(32, 32)>>>(Wv, bhi, blo);
    hgemm_kernel<<<ggrid, 256, HG_SMEM>>>(ahi, alo, bhi, blo, bv, nullptr,
                                          vthi, vtlo, M_ROWS, D_MODEL, D_MODEL,
                                          2, 1.0f);

    // attention -> ahi/alo (bf16 hi/lo row-major = A of output projection)
    flash_hmma_kernel<<<dim3(SEQ / 128, BATCH * NUM_HEADS), 256, FA_SMEM>>>(
        qhi, qlo, khi, klo, vthi, vtlo, ahi, alo);

    // output projection -> out (fp32 + bias)
    splitT_kernel<<<dim3(32, 32), dim3(32, 32)>>>(Wo, bhi, blo);
    hgemm_kernel<<<ggrid, 256, HG_SMEM>>>(ahi, alo, bhi, blo, bo, out,
                                          nullptr, nullptr, M_ROWS, D_MODEL,
                                          D_MODEL, 0, 1.0f);
}